// round 5
// baseline (speedup 1.0000x reference)
#include <cuda_runtime.h>

// Problem constants
#define NT 50000
#define NS 100000
#define NE 400000
#define CIN 128
#define CCH 256

// Scratch (device globals — no allocation allowed)
__device__ float g_sup0[(size_t)NS * CCH];
__device__ float g_sup1[(size_t)NS * CCH];
__device__ float g_a0[(size_t)NT * CCH];
__device__ float g_b0[(size_t)NT * CCH];
__device__ float g_a1[(size_t)NT * CCH];
__device__ float g_b1[(size_t)NT * CCH];

// ---------------------------------------------------------------------------
// Tiled fp32 GEMM: C[M,256] = op(A[M,K] @ B[K,256] (+bias) (+C) ) (ReLU opt)
// BM=128, BN=64, BK=16, 256 threads, each thread 8x4 outputs.
// N fixed at 256, K multiple of 16, M guarded.
// ---------------------------------------------------------------------------
#define BM 128
#define BN 64
#define BK 16

template <bool BIAS, bool RELU, bool ACCUM>
__global__ __launch_bounds__(256) void gemm_kernel(
    const float* __restrict__ A, const float* __restrict__ B,
    const float* __restrict__ bias, float* __restrict__ C,
    int M, int K)
{
    const int N = CCH;
    __shared__ float As[BK][BM];
    __shared__ float Bs[BK][BN];

    const int bm = blockIdx.x * BM;
    const int bn = blockIdx.y * BN;
    const int tid = threadIdx.x;
    const int tx = tid & 15;   // col group: 4 cols
    const int ty = tid >> 4;   // row group: 8 rows

    float acc[8][4];
#pragma unroll
    for (int i = 0; i < 8; i++)
#pragma unroll
        for (int j = 0; j < 4; j++) acc[i][j] = 0.0f;

    const int a_r = tid >> 2;        // 0..63
    const int a_k = (tid & 3) * 4;   // 0,4,8,12
    const int b_k = tid >> 4;        // 0..15
    const int b_n = (tid & 15) * 4;  // 0..60

    for (int k0 = 0; k0 < K; k0 += BK) {
        // Load A tile (128x16) as float4 per row-chunk, store transposed
#pragma unroll
        for (int i = 0; i < 2; i++) {
            int row = bm + a_r + i * 64;
            float4 a;
            if (row < M) {
                a = *(const float4*)(A + (size_t)row * K + k0 + a_k);
            } else {
                a = make_float4(0.f, 0.f, 0.f, 0.f);
            }
            As[a_k + 0][a_r + i * 64] = a.x;
            As[a_k + 1][a_r + i * 64] = a.y;
            As[a_k + 2][a_r + i * 64] = a.z;
            As[a_k + 3][a_r + i * 64] = a.w;
        }
        // Load B tile (16x64)
        {
            float4 b = *(const float4*)(B + (size_t)(k0 + b_k) * N + bn + b_n);
            *(float4*)&Bs[b_k][b_n] = b;
        }
        __syncthreads();

#pragma unroll
        for (int k = 0; k < BK; k++) {
            float4 bv = *(float4*)&Bs[k][tx * 4];
            float4 am0 = *(float4*)&As[k][ty * 8];
            float4 am1 = *(float4*)&As[k][ty * 8 + 4];
            float am[8] = {am0.x, am0.y, am0.z, am0.w, am1.x, am1.y, am1.z, am1.w};
#pragma unroll
            for (int i = 0; i < 8; i++) {
                acc[i][0] += am[i] * bv.x;
                acc[i][1] += am[i] * bv.y;
                acc[i][2] += am[i] * bv.z;
                acc[i][3] += am[i] * bv.w;
            }
        }
        __syncthreads();
    }

    float4 bv = make_float4(0.f, 0.f, 0.f, 0.f);
    if (BIAS) bv = *(const float4*)(bias + bn + tx * 4);

#pragma unroll
    for (int i = 0; i < 8; i++) {
        int row = bm + ty * 8 + i;
        if (row >= M) continue;
        float* cp = C + (size_t)row * N + bn + tx * 4;
        float4 o;
        o.x = acc[i][0] + bv.x;
        o.y = acc[i][1] + bv.y;
        o.z = acc[i][2] + bv.z;
        o.w = acc[i][3] + bv.w;
        if (ACCUM) {
            float4 c = *(float4*)cp;
            o.x += c.x; o.y += c.y; o.z += c.z; o.w += c.w;
        }
        if (RELU) {
            o.x = fmaxf(o.x, 0.f); o.y = fmaxf(o.y, 0.f);
            o.z = fmaxf(o.z, 0.f); o.w = fmaxf(o.w, 0.f);
        }
        *(float4*)cp = o;
    }
}

// ---------------------------------------------------------------------------
// Edge scatter: agg[rows[e]] += vals[e] * support[cols[e]]  (256 channels)
// 64 threads per edge, each handles 4 channels (float4 gather + 4 atomics)
// ---------------------------------------------------------------------------
__global__ __launch_bounds__(256) void scatter_kernel(
    const float* __restrict__ sup, const float* __restrict__ vals,
    const int* __restrict__ rows, const int* __restrict__ cols,
    float* __restrict__ agg)
{
    long long idx = (long long)blockIdx.x * blockDim.x + threadIdx.x;
    if (idx >= (long long)NE * 64) return;
    int e = (int)(idx >> 6);
    int q = (int)(idx & 63);
    int r = __ldg(rows + e);
    int c = __ldg(cols + e);
    float v = __ldg(vals + e);
    float4 s = *(const float4*)(sup + (size_t)c * CCH + q * 4);
    float* dst = agg + (size_t)r * CCH + q * 4;
    atomicAdd(dst + 0, v * s.x);
    atomicAdd(dst + 1, v * s.y);
    atomicAdd(dst + 2, v * s.z);
    atomicAdd(dst + 3, v * s.w);
}

// ---------------------------------------------------------------------------
extern "C" void kernel_launch(void* const* d_in, const int* in_sizes, int n_in,
                              void* d_out, int out_size)
{
    const float* x_t  = (const float*)d_in[0];
    const float* xs0  = (const float*)d_in[1];
    const float* xs1  = (const float*)d_in[2];
    const float* v0   = (const float*)d_in[3];
    const float* v1   = (const float*)d_in[4];
    const int*   r0   = (const int*)d_in[5];
    const int*   c0   = (const int*)d_in[6];
    const int*   r1   = (const int*)d_in[7];
    const int*   c1   = (const int*)d_in[8];
    const float* W0   = (const float*)d_in[9];
    const float* W1   = (const float*)d_in[10];
    const float* mW0  = (const float*)d_in[11];
    const float* mb0  = (const float*)d_in[12];
    const float* mW1  = (const float*)d_in[13];
    const float* mb1  = (const float*)d_in[14];
    const float* Wm   = (const float*)d_in[15];
    const float* bm   = (const float*)d_in[16];
    float* out = (float*)d_out;

    float *sup0, *sup1, *a0, *b0, *a1, *b1;
    cudaGetSymbolAddress((void**)&sup0, g_sup0);
    cudaGetSymbolAddress((void**)&sup1, g_sup1);
    cudaGetSymbolAddress((void**)&a0, g_a0);
    cudaGetSymbolAddress((void**)&b0, g_b0);
    cudaGetSymbolAddress((void**)&a1, g_a1);
    cudaGetSymbolAddress((void**)&b1, g_b1);

    dim3 blk(256);
    dim3 gS((NS + BM - 1) / BM, CCH / BN);  // support GEMMs
    dim3 gT((NT + BM - 1) / BM, CCH / BN);  // target-side GEMMs

    // support = x_src @ W
    gemm_kernel<false, false, false><<<gS, blk>>>(xs0, W0, nullptr, sup0, NS, CIN);
    gemm_kernel<false, false, false><<<gS, blk>>>(xs1, W1, nullptr, sup1, NS, CIN);

    // agg init = x_target (epsilon = 0)
    cudaMemcpyAsync(a0, x_t, sizeof(float) * (size_t)NT * CCH, cudaMemcpyDeviceToDevice);
    cudaMemcpyAsync(a1, x_t, sizeof(float) * (size_t)NT * CCH, cudaMemcpyDeviceToDevice);

    // sparse scatter-add
    int sblocks = (int)(((long long)NE * 64 + 255) / 256);
    scatter_kernel<<<sblocks, blk>>>(sup0, v0, r0, c0, a0);
    scatter_kernel<<<sblocks, blk>>>(sup1, v1, r1, c1, a1);

    // MLP branch 0: a0 -> b0 -> a0 -> b0
    gemm_kernel<true, true, false><<<gT, blk>>>(a0, mW0,            mb0,       b0, NT, CCH);
    gemm_kernel<true, true, false><<<gT, blk>>>(b0, mW0 + 65536,    mb0 + 256, a0, NT, CCH);
    gemm_kernel<true, true, false><<<gT, blk>>>(a0, mW0 + 131072,   mb0 + 512, b0, NT, CCH);

    // MLP branch 1: a1 -> b1 -> a1 -> b1
    gemm_kernel<true, true, false><<<gT, blk>>>(a1, mW1,            mb1,       b1, NT, CCH);
    gemm_kernel<true, true, false><<<gT, blk>>>(b1, mW1 + 65536,    mb1 + 256, a1, NT, CCH);
    gemm_kernel<true, true, false><<<gT, blk>>>(a1, mW1 + 131072,   mb1 + 512, b1, NT, CCH);

    // merge: out = h0 @ Wm[:256] + bm ; out += h1 @ Wm[256:]
    gemm_kernel<true,  false, false><<<gT, blk>>>(b0, Wm,         bm,      out, NT, CCH);
    gemm_kernel<false, false, true ><<<gT, blk>>>(b1, Wm + 65536, nullptr, out, NT, CCH);
}

// round 7
// speedup vs baseline: 1.5784x; 1.5784x over previous
#include <cuda_runtime.h>
#include <cuda_bf16.h>
#include <cstdint>

// Problem constants
#define NT 50000
#define NS 100000
#define NE 400000
#define CIN 128
#define CCH 256

// ---------------------------------------------------------------------------
// Scratch (device globals — no allocation allowed)
// ---------------------------------------------------------------------------
__device__ float g_sup0[(size_t)NS * CCH];
__device__ float g_sup1[(size_t)NS * CCH];
__device__ float g_a0[(size_t)NT * CCH];
__device__ float g_b0[(size_t)NT * CCH];
__device__ float g_a1[(size_t)NT * CCH];
__device__ float g_b1[(size_t)NT * CCH];
// bf16 transposed+split weights: [hi | lo] blocks, each [N=256, K] K-major
__device__ __nv_bfloat16 g_wt0[2 * 256 * 128];        // W0^T
__device__ __nv_bfloat16 g_wt1[2 * 256 * 128];        // W1^T
__device__ __nv_bfloat16 g_mwt0[3 * 2 * 256 * 256];   // per-layer [hi|lo]
__device__ __nv_bfloat16 g_mwt1[3 * 2 * 256 * 256];
__device__ __nv_bfloat16 g_wmt[2 * 256 * 512];        // Wm^T (K=512)

// ---------------------------------------------------------------------------
// Helpers
// ---------------------------------------------------------------------------
__device__ __forceinline__ uint32_t smem_u32(const void* p) {
    uint32_t a;
    asm("{ .reg .u64 t; cvta.to.shared.u64 t, %1; cvt.u32.u64 %0, t; }"
        : "=r"(a) : "l"(p));
    return a;
}

__device__ __forceinline__ void ldsm4(uint32_t* r, uint32_t addr) {
    asm volatile("ldmatrix.sync.aligned.m8n8.x4.shared.b16 {%0,%1,%2,%3}, [%4];"
                 : "=r"(r[0]), "=r"(r[1]), "=r"(r[2]), "=r"(r[3]) : "r"(addr));
}

__device__ __forceinline__ void mma16816(float* d, const uint32_t* a, const uint32_t* b) {
    asm volatile(
        "mma.sync.aligned.m16n8k16.row.col.f32.bf16.bf16.f32 "
        "{%0,%1,%2,%3}, {%4,%5,%6,%7}, {%8,%9}, {%0,%1,%2,%3};"
        : "+f"(d[0]), "+f"(d[1]), "+f"(d[2]), "+f"(d[3])
        : "r"(a[0]), "r"(a[1]), "r"(a[2]), "r"(a[3]), "r"(b[0]), "r"(b[1]));
}

__device__ __forceinline__ uint32_t pack2(__nv_bfloat16 x, __nv_bfloat16 y) {
    return ((uint32_t)__bfloat16_as_ushort(y) << 16) | __bfloat16_as_ushort(x);
}

// ---------------------------------------------------------------------------
// Weight prep: W [K, 256] fp32 -> Wt_hi/Wt_lo [256, K] bf16 (K-major)
// ---------------------------------------------------------------------------
__global__ __launch_bounds__(256) void prep_w(
    const float* __restrict__ W, __nv_bfloat16* __restrict__ hi,
    __nv_bfloat16* __restrict__ lo, int K)
{
    int idx = blockIdx.x * 256 + threadIdx.x;
    if (idx >= K * 256) return;
    int k = idx >> 8;
    int n = idx & 255;
    float x = W[idx];
    __nv_bfloat16 h = __float2bfloat16(x);
    float r = x - __bfloat162float(h);
    hi[(size_t)n * K + k] = h;
    lo[(size_t)n * K + k] = __float2bfloat16(r);
}

// ---------------------------------------------------------------------------
// Split-bf16 mma.sync GEMM:  C[M,256] = relu?( A[M,Ktot] @ Bt^T + bias )
// Bt pre-split bf16 [256, Ktot] K-major (hi, lo). A split on the fly.
// A2: optional second A source for k >= 256 (merge GEMM, Ktot=512).
// Block: 256 thr (8 warps), tile 128x128, BK=32, double-buffered smem.
// Warp (warpM 0-1, warpN 0-3): 64x32 out = 4x4 m16n8k16 tiles.
// Smem row stride 80B (64B data + 16B pad) -> conflict-free ldmatrix.
// ---------------------------------------------------------------------------
#define ROWB 80
#define BUF  (128 * ROWB)          /* 10240 B per operand buffer */
#define STAGE (4 * BUF)            /* AH, AL, BH, BL = 40960 B   */
#define SMEMT (2 * STAGE)          /* 81920 B                    */

template <bool BIAS, bool RELU>
__global__ __launch_bounds__(256, 1) void mma_gemm(
    const float* __restrict__ A, const float* __restrict__ A2,
    const __nv_bfloat16* __restrict__ Bhi, const __nv_bfloat16* __restrict__ Blo,
    const float* __restrict__ bias, float* __restrict__ C,
    int M, int Ktot, int lda)
{
    extern __shared__ char smem[];
    const uint32_t sb = smem_u32(smem);
    const int tid = threadIdx.x;
    const int wid = tid >> 5;
    const int lane = tid & 31;
    const int warpM = wid >> 2;   // 0-1 -> 64 rows each
    const int warpN = wid & 3;    // 0-3 -> 32 cols each
    const int bm = blockIdx.x * 128;
    const int bn = blockIdx.y * 128;

    float acc[4][4][4];
#pragma unroll
    for (int i = 0; i < 4; i++)
#pragma unroll
        for (int j = 0; j < 4; j++)
#pragma unroll
            for (int q = 0; q < 4; q++) acc[i][j][q] = 0.0f;

    float4 aReg[4];
    uint4 bhReg[2], blReg[2];

    auto loadG = [&](int c) {
        const int k0 = c << 5;
        const float* Ap = A;
        int kk = k0;
        if (A2 != nullptr && k0 >= 256) { Ap = A2; kk = k0 - 256; }
#pragma unroll
        for (int i = 0; i < 4; i++) {
            int idx = i * 256 + tid;
            int r = idx >> 3, c4 = idx & 7;
            int row = bm + r;
            aReg[i] = (row < M)
                ? __ldg((const float4*)(Ap + (size_t)row * lda + kk) + c4)
                : make_float4(0.f, 0.f, 0.f, 0.f);
        }
#pragma unroll
        for (int i = 0; i < 2; i++) {
            int idx = i * 256 + tid;
            int r = idx >> 2, ch = idx & 3;
            size_t g = (size_t)(bn + r) * Ktot + k0 + ch * 8;
            bhReg[i] = __ldg((const uint4*)(Bhi + g));
            blReg[i] = __ldg((const uint4*)(Blo + g));
        }
    };

    auto storeS = [&](int s) {
        char* st = smem + s * STAGE;
#pragma unroll
        for (int i = 0; i < 4; i++) {
            int idx = i * 256 + tid;
            int r = idx >> 3, c4 = idx & 7;
            uint32_t off = (uint32_t)(r * ROWB + (c4 >> 1) * 16 + (c4 & 1) * 8);
            float4 v = aReg[i];
            __nv_bfloat16 h0 = __float2bfloat16(v.x);
            __nv_bfloat16 h1 = __float2bfloat16(v.y);
            __nv_bfloat16 h2 = __float2bfloat16(v.z);
            __nv_bfloat16 h3 = __float2bfloat16(v.w);
            uint2 ph, pl;
            ph.x = pack2(h0, h1);
            ph.y = pack2(h2, h3);
            pl.x = pack2(__float2bfloat16(v.x - __bfloat162float(h0)),
                         __float2bfloat16(v.y - __bfloat162float(h1)));
            pl.y = pack2(__float2bfloat16(v.z - __bfloat162float(h2)),
                         __float2bfloat16(v.w - __bfloat162float(h3)));
            *(uint2*)(st + off) = ph;
            *(uint2*)(st + BUF + off) = pl;
        }
#pragma unroll
        for (int i = 0; i < 2; i++) {
            int idx = i * 256 + tid;
            int r = idx >> 2, ch = idx & 3;
            uint32_t off = (uint32_t)(r * ROWB + ch * 16);
            *(uint4*)(st + 2 * BUF + off) = bhReg[i];
            *(uint4*)(st + 3 * BUF + off) = blReg[i];
        }
    };

    auto mmaS = [&](int s) {
        const uint32_t base = sb + s * STAGE;
#pragma unroll
        for (int ks = 0; ks < 2; ks++) {
            uint32_t bhf[4][2], blf[4][2];
#pragma unroll
            for (int ntp = 0; ntp < 2; ntp++) {
                int rB = warpN * 32 + ntp * 16 + ((lane >> 4) & 1) * 8 + (lane & 7);
                int cB = ks * 2 + ((lane >> 3) & 1);
                uint32_t addr = base + 2 * BUF + rB * ROWB + cB * 16;
                uint32_t q[4];
                ldsm4(q, addr);
                bhf[ntp * 2][0] = q[0]; bhf[ntp * 2][1] = q[1];
                bhf[ntp * 2 + 1][0] = q[2]; bhf[ntp * 2 + 1][1] = q[3];
                ldsm4(q, addr + BUF);
                blf[ntp * 2][0] = q[0]; blf[ntp * 2][1] = q[1];
                blf[ntp * 2 + 1][0] = q[2]; blf[ntp * 2 + 1][1] = q[3];
            }
#pragma unroll
            for (int mt = 0; mt < 4; mt++) {
                int rA = warpM * 64 + mt * 16 + (lane & 15);
                int cA = ks * 2 + (lane >> 4);
                uint32_t addr = base + rA * ROWB + cA * 16;
                uint32_t ah[4], al[4];
                ldsm4(ah, addr);
                ldsm4(al, addr + BUF);
#pragma unroll
                for (int nt = 0; nt < 4; nt++) {
                    mma16816(acc[mt][nt], ah, bhf[nt]);
                    mma16816(acc[mt][nt], ah, blf[nt]);
                    mma16816(acc[mt][nt], al, bhf[nt]);
                }
            }
        }
    };

    const int nch = Ktot >> 5;
    loadG(0);
    storeS(0);
    __syncthreads();
    for (int c = 0; c < nch; c++) {
        if (c + 1 < nch) loadG(c + 1);
        mmaS(c & 1);
        if (c + 1 < nch) storeS((c + 1) & 1);
        __syncthreads();
    }

    // Epilogue
#pragma unroll
    for (int mt = 0; mt < 4; mt++) {
        int row0 = bm + warpM * 64 + mt * 16 + (lane >> 2);
#pragma unroll
        for (int nt = 0; nt < 4; nt++) {
            int col = bn + warpN * 32 + nt * 8 + (lane & 3) * 2;
            float bx = 0.f, by = 0.f;
            if (BIAS) { bx = __ldg(bias + col); by = __ldg(bias + col + 1); }
            float2 v0 = make_float2(acc[mt][nt][0] + bx, acc[mt][nt][1] + by);
            float2 v1 = make_float2(acc[mt][nt][2] + bx, acc[mt][nt][3] + by);
            if (RELU) {
                v0.x = fmaxf(v0.x, 0.f); v0.y = fmaxf(v0.y, 0.f);
                v1.x = fmaxf(v1.x, 0.f); v1.y = fmaxf(v1.y, 0.f);
            }
            if (row0 < M)     *(float2*)(C + (size_t)row0 * 256 + col) = v0;
            if (row0 + 8 < M) *(float2*)(C + (size_t)(row0 + 8) * 256 + col) = v1;
        }
    }
}

// ---------------------------------------------------------------------------
// Edge scatter: agg[rows[e]] += vals[e] * support[cols[e]]  (256 channels)
// ---------------------------------------------------------------------------
__global__ __launch_bounds__(256) void scatter_kernel(
    const float* __restrict__ sup, const float* __restrict__ vals,
    const int* __restrict__ rows, const int* __restrict__ cols,
    float* __restrict__ agg)
{
    long long idx = (long long)blockIdx.x * blockDim.x + threadIdx.x;
    if (idx >= (long long)NE * 64) return;
    int e = (int)(idx >> 6);
    int q = (int)(idx & 63);
    int r = __ldg(rows + e);
    int c = __ldg(cols + e);
    float v = __ldg(vals + e);
    float4 s = *(const float4*)(sup + (size_t)c * CCH + q * 4);
    float* dst = agg + (size_t)r * CCH + q * 4;
    atomicAdd(dst + 0, v * s.x);
    atomicAdd(dst + 1, v * s.y);
    atomicAdd(dst + 2, v * s.z);
    atomicAdd(dst + 3, v * s.w);
}

// ---------------------------------------------------------------------------
extern "C" void kernel_launch(void* const* d_in, const int* in_sizes, int n_in,
                              void* d_out, int out_size)
{
    const float* x_t  = (const float*)d_in[0];
    const float* xs0  = (const float*)d_in[1];
    const float* xs1  = (const float*)d_in[2];
    const float* v0   = (const float*)d_in[3];
    const float* v1   = (const float*)d_in[4];
    const int*   r0   = (const int*)d_in[5];
    const int*   c0   = (const int*)d_in[6];
    const int*   r1   = (const int*)d_in[7];
    const int*   c1   = (const int*)d_in[8];
    const float* W0   = (const float*)d_in[9];
    const float* W1   = (const float*)d_in[10];
    const float* mW0  = (const float*)d_in[11];
    const float* mb0  = (const float*)d_in[12];
    const float* mW1  = (const float*)d_in[13];
    const float* mb1  = (const float*)d_in[14];
    const float* Wm   = (const float*)d_in[15];
    const float* bmv  = (const float*)d_in[16];
    float* out = (float*)d_out;

    float *sup0, *sup1, *a0, *b0, *a1, *b1;
    __nv_bfloat16 *wt0, *wt1, *mwt0, *mwt1, *wmt;
    cudaGetSymbolAddress((void**)&sup0, g_sup0);
    cudaGetSymbolAddress((void**)&sup1, g_sup1);
    cudaGetSymbolAddress((void**)&a0, g_a0);
    cudaGetSymbolAddress((void**)&b0, g_b0);
    cudaGetSymbolAddress((void**)&a1, g_a1);
    cudaGetSymbolAddress((void**)&b1, g_b1);
    cudaGetSymbolAddress((void**)&wt0, g_wt0);
    cudaGetSymbolAddress((void**)&wt1, g_wt1);
    cudaGetSymbolAddress((void**)&mwt0, g_mwt0);
    cudaGetSymbolAddress((void**)&mwt1, g_mwt1);
    cudaGetSymbolAddress((void**)&wmt, g_wmt);

    cudaFuncSetAttribute(mma_gemm<false, false>,
                         cudaFuncAttributeMaxDynamicSharedMemorySize, SMEMT);
    cudaFuncSetAttribute(mma_gemm<true, true>,
                         cudaFuncAttributeMaxDynamicSharedMemorySize, SMEMT);
    cudaFuncSetAttribute(mma_gemm<true, false>,
                         cudaFuncAttributeMaxDynamicSharedMemorySize, SMEMT);

    // ---- Weight prep: transpose + hi/lo bf16 split ----
    prep_w<<<(128 * 256 + 255) / 256, 256>>>(W0, wt0, wt0 + 256 * 128, 128);
    prep_w<<<(128 * 256 + 255) / 256, 256>>>(W1, wt1, wt1 + 256 * 128, 128);
    for (int l = 0; l < 3; l++) {
        prep_w<<<(256 * 256 + 255) / 256, 256>>>(
            mW0 + (size_t)l * 65536, mwt0 + (size_t)(2 * l) * 65536,
            mwt0 + (size_t)(2 * l + 1) * 65536, 256);
        prep_w<<<(256 * 256 + 255) / 256, 256>>>(
            mW1 + (size_t)l * 65536, mwt1 + (size_t)(2 * l) * 65536,
            mwt1 + (size_t)(2 * l + 1) * 65536, 256);
    }
    prep_w<<<(512 * 256 + 255) / 256, 256>>>(Wm, wmt, wmt + 256 * 512, 512);

    dim3 blk(256);
    dim3 gS((NS + 127) / 128, 2);   // support GEMMs: 782 x 2
    dim3 gT((NT + 127) / 128, 2);   // target GEMMs:  391 x 2

    // support = x_src @ W
    mma_gemm<false, false><<<gS, blk, SMEMT>>>(
        xs0, nullptr, wt0, wt0 + 256 * 128, nullptr, sup0, NS, 128, 128);
    mma_gemm<false, false><<<gS, blk, SMEMT>>>(
        xs1, nullptr, wt1, wt1 + 256 * 128, nullptr, sup1, NS, 128, 128);

    // agg init = x_target (epsilon = 0)
    cudaMemcpyAsync(a0, x_t, sizeof(float) * (size_t)NT * CCH, cudaMemcpyDeviceToDevice);
    cudaMemcpyAsync(a1, x_t, sizeof(float) * (size_t)NT * CCH, cudaMemcpyDeviceToDevice);

    // sparse scatter-add
    int sblocks = (int)(((long long)NE * 64 + 255) / 256);
    scatter_kernel<<<sblocks, blk>>>(sup0, v0, r0, c0, a0);
    scatter_kernel<<<sblocks, blk>>>(sup1, v1, r1, c1, a1);

    // MLP branch 0: a0 -> b0 -> a0 -> b0
    mma_gemm<true, true><<<gT, blk, SMEMT>>>(
        a0, nullptr, mwt0, mwt0 + 65536, mb0, b0, NT, 256, 256);
    mma_gemm<true, true><<<gT, blk, SMEMT>>>(
        b0, nullptr, mwt0 + 2 * 65536, mwt0 + 3 * 65536, mb0 + 256, a0, NT, 256, 256);
    mma_gemm<true, true><<<gT, blk, SMEMT>>>(
        a0, nullptr, mwt0 + 4 * 65536, mwt0 + 5 * 65536, mb0 + 512, b0, NT, 256, 256);

    // MLP branch 1: a1 -> b1 -> a1 -> b1
    mma_gemm<true, true><<<gT, blk, SMEMT>>>(
        a1, nullptr, mwt1, mwt1 + 65536, mb1, b1, NT, 256, 256);
    mma_gemm<true, true><<<gT, blk, SMEMT>>>(
        b1, nullptr, mwt1 + 2 * 65536, mwt1 + 3 * 65536, mb1 + 256, a1, NT, 256, 256);
    mma_gemm<true, true><<<gT, blk, SMEMT>>>(
        a1, nullptr, mwt1 + 4 * 65536, mwt1 + 5 * 65536, mb1 + 512, b1, NT, 256, 256);

    // merge: out = [h0, h1] @ Wm + bm   (single K=512 GEMM, dual A sources)
    mma_gemm<true, false><<<gT, blk, SMEMT>>>(
        b0, b1, wmt, wmt + 256 * 512, bmv, out, NT, 512, 256);
}

// round 8
// speedup vs baseline: 2.0587x; 1.3043x over previous
#include <cuda_runtime.h>
#include <cuda_bf16.h>
#include <cstdint>

// Problem constants
#define NT 50000
#define NS 100000
#define NE 400000
#define CIN 128
#define CCH 256

// ---------------------------------------------------------------------------
// Scratch (device globals — no allocation allowed)
// ---------------------------------------------------------------------------
__device__ float g_sup0[(size_t)NS * CCH];
__device__ float g_sup1[(size_t)NS * CCH];
__device__ float g_a0[(size_t)NT * CCH];
__device__ float g_b0[(size_t)NT * CCH];
__device__ float g_a1[(size_t)NT * CCH];
__device__ float g_b1[(size_t)NT * CCH];
// bf16 transposed+split weights: [hi | lo] blocks, each [N=256, K] K-major
__device__ __nv_bfloat16 g_wt0[2 * 256 * 128];        // W0^T
__device__ __nv_bfloat16 g_wt1[2 * 256 * 128];        // W1^T
__device__ __nv_bfloat16 g_mwt0[3 * 2 * 256 * 256];   // per-layer [hi|lo]
__device__ __nv_bfloat16 g_mwt1[3 * 2 * 256 * 256];
__device__ __nv_bfloat16 g_wmt[2 * 256 * 512];        // Wm^T (K=512)

// ---------------------------------------------------------------------------
// Helpers
// ---------------------------------------------------------------------------
__device__ __forceinline__ uint32_t smem_u32(const void* p) {
    uint32_t a;
    asm("{ .reg .u64 t; cvta.to.shared.u64 t, %1; cvt.u32.u64 %0, t; }"
        : "=r"(a) : "l"(p));
    return a;
}

__device__ __forceinline__ void ldsm4(uint32_t* r, uint32_t addr) {
    asm volatile("ldmatrix.sync.aligned.m8n8.x4.shared.b16 {%0,%1,%2,%3}, [%4];"
                 : "=r"(r[0]), "=r"(r[1]), "=r"(r[2]), "=r"(r[3]) : "r"(addr));
}

__device__ __forceinline__ void mma16816(float* d, const uint32_t* a, const uint32_t* b) {
    asm volatile(
        "mma.sync.aligned.m16n8k16.row.col.f32.bf16.bf16.f32 "
        "{%0,%1,%2,%3}, {%4,%5,%6,%7}, {%8,%9}, {%0,%1,%2,%3};"
        : "+f"(d[0]), "+f"(d[1]), "+f"(d[2]), "+f"(d[3])
        : "r"(a[0]), "r"(a[1]), "r"(a[2]), "r"(a[3]), "r"(b[0]), "r"(b[1]));
}

__device__ __forceinline__ uint32_t pack2(__nv_bfloat16 x, __nv_bfloat16 y) {
    return ((uint32_t)__bfloat16_as_ushort(y) << 16) | __bfloat16_as_ushort(x);
}

// ---------------------------------------------------------------------------
// Weight prep: W [K, 256] fp32 -> Wt_hi/Wt_lo [256, K] bf16 (K-major)
// Batched over grid.y layers (layer l: W + l*K*256, hi/lo + l*2*K*256)
// ---------------------------------------------------------------------------
__global__ __launch_bounds__(256) void prep_w(
    const float* __restrict__ W, __nv_bfloat16* __restrict__ hi,
    __nv_bfloat16* __restrict__ lo, int K)
{
    int l = blockIdx.y;
    const float* Wl = W + (size_t)l * K * 256;
    __nv_bfloat16* hil = hi + (size_t)l * 2 * K * 256;
    __nv_bfloat16* lol = lo + (size_t)l * 2 * K * 256;
    int idx = blockIdx.x * 256 + threadIdx.x;
    if (idx >= K * 256) return;
    int k = idx >> 8;
    int n = idx & 255;
    float x = Wl[idx];
    __nv_bfloat16 h = __float2bfloat16(x);
    float r = x - __bfloat162float(h);
    hil[(size_t)n * K + k] = h;
    lol[(size_t)n * K + k] = __float2bfloat16(r);
}

// ---------------------------------------------------------------------------
// Split-bf16 mma.sync GEMM:  C[M,256] = relu?( A[M,Ktot] @ Bt^T + bias )
// Bt pre-split bf16 [256, Ktot] K-major (hi, lo). A split on the fly.
// A2: optional second A source for k >= 256 (merge GEMM, Ktot=512).
// Block: 256 thr (8 warps), tile 128x128, BK=32, double-buffered smem.
// Warp (warpM 0-1, warpN 0-3): 64x32 out = 4x4 m16n8k16 tiles.
// Smem row stride 80B (64B data + 16B pad) -> conflict-free ldmatrix.
// Occupancy 2 blocks/SM (160KB smem, regs capped at 128).
// ---------------------------------------------------------------------------
#define ROWB 80
#define BUF  (128 * ROWB)          /* 10240 B per operand buffer */
#define STAGE (4 * BUF)            /* AH, AL, BH, BL = 40960 B   */
#define SMEMT (2 * STAGE)          /* 81920 B                    */

template <bool BIAS, bool RELU>
__global__ __launch_bounds__(256, 2) void mma_gemm(
    const float* __restrict__ A, const float* __restrict__ A2,
    const __nv_bfloat16* __restrict__ Bhi, const __nv_bfloat16* __restrict__ Blo,
    const float* __restrict__ bias, float* __restrict__ C,
    int M, int Ktot, int lda)
{
    extern __shared__ char smem[];
    const uint32_t sb = smem_u32(smem);
    const int tid = threadIdx.x;
    const int wid = tid >> 5;
    const int lane = tid & 31;
    const int warpM = wid >> 2;   // 0-1 -> 64 rows each
    const int warpN = wid & 3;    // 0-3 -> 32 cols each
    const int bm = blockIdx.x * 128;
    const int bn = blockIdx.y * 128;

    float acc[4][4][4];
#pragma unroll
    for (int i = 0; i < 4; i++)
#pragma unroll
        for (int j = 0; j < 4; j++)
#pragma unroll
            for (int q = 0; q < 4; q++) acc[i][j][q] = 0.0f;

    float4 aReg[4];
    uint4 bhReg[2], blReg[2];

    auto loadG = [&](int c) {
        const int k0 = c << 5;
        const float* Ap = A;
        int kk = k0;
        if (A2 != nullptr && k0 >= 256) { Ap = A2; kk = k0 - 256; }
#pragma unroll
        for (int i = 0; i < 4; i++) {
            int idx = i * 256 + tid;
            int r = idx >> 3, c4 = idx & 7;
            int row = bm + r;
            aReg[i] = (row < M)
                ? __ldg((const float4*)(Ap + (size_t)row * lda + kk) + c4)
                : make_float4(0.f, 0.f, 0.f, 0.f);
        }
#pragma unroll
        for (int i = 0; i < 2; i++) {
            int idx = i * 256 + tid;
            int r = idx >> 2, ch = idx & 3;
            size_t g = (size_t)(bn + r) * Ktot + k0 + ch * 8;
            bhReg[i] = __ldg((const uint4*)(Bhi + g));
            blReg[i] = __ldg((const uint4*)(Blo + g));
        }
    };

    auto storeS = [&](int s) {
        char* st = smem + s * STAGE;
#pragma unroll
        for (int i = 0; i < 4; i++) {
            int idx = i * 256 + tid;
            int r = idx >> 3, c4 = idx & 7;
            uint32_t off = (uint32_t)(r * ROWB + (c4 >> 1) * 16 + (c4 & 1) * 8);
            float4 v = aReg[i];
            __nv_bfloat16 h0 = __float2bfloat16(v.x);
            __nv_bfloat16 h1 = __float2bfloat16(v.y);
            __nv_bfloat16 h2 = __float2bfloat16(v.z);
            __nv_bfloat16 h3 = __float2bfloat16(v.w);
            uint2 ph, pl;
            ph.x = pack2(h0, h1);
            ph.y = pack2(h2, h3);
            pl.x = pack2(__float2bfloat16(v.x - __bfloat162float(h0)),
                         __float2bfloat16(v.y - __bfloat162float(h1)));
            pl.y = pack2(__float2bfloat16(v.z - __bfloat162float(h2)),
                         __float2bfloat16(v.w - __bfloat162float(h3)));
            *(uint2*)(st + off) = ph;
            *(uint2*)(st + BUF + off) = pl;
        }
#pragma unroll
        for (int i = 0; i < 2; i++) {
            int idx = i * 256 + tid;
            int r = idx >> 2, ch = idx & 3;
            uint32_t off = (uint32_t)(r * ROWB + ch * 16);
            *(uint4*)(st + 2 * BUF + off) = bhReg[i];
            *(uint4*)(st + 3 * BUF + off) = blReg[i];
        }
    };

    auto mmaS = [&](int s) {
        const uint32_t base = sb + s * STAGE;
#pragma unroll
        for (int ks = 0; ks < 2; ks++) {
            uint32_t bhf[4][2], blf[4][2];
#pragma unroll
            for (int ntp = 0; ntp < 2; ntp++) {
                int rB = warpN * 32 + ntp * 16 + ((lane >> 4) & 1) * 8 + (lane & 7);
                int cB = ks * 2 + ((lane >> 3) & 1);
                uint32_t addr = base + 2 * BUF + rB * ROWB + cB * 16;
                uint32_t q[4];
                ldsm4(q, addr);
                bhf[ntp * 2][0] = q[0]; bhf[ntp * 2][1] = q[1];
                bhf[ntp * 2 + 1][0] = q[2]; bhf[ntp * 2 + 1][1] = q[3];
                ldsm4(q, addr + BUF);
                blf[ntp * 2][0] = q[0]; blf[ntp * 2][1] = q[1];
                blf[ntp * 2 + 1][0] = q[2]; blf[ntp * 2 + 1][1] = q[3];
            }
#pragma unroll
            for (int mt = 0; mt < 4; mt++) {
                int rA = warpM * 64 + mt * 16 + (lane & 15);
                int cA = ks * 2 + (lane >> 4);
                uint32_t addr = base + rA * ROWB + cA * 16;
                uint32_t ah[4], al[4];
                ldsm4(ah, addr);
                ldsm4(al, addr + BUF);
#pragma unroll
                for (int nt = 0; nt < 4; nt++) {
                    mma16816(acc[mt][nt], ah, bhf[nt]);
                    mma16816(acc[mt][nt], ah, blf[nt]);
                    mma16816(acc[mt][nt], al, bhf[nt]);
                }
            }
        }
    };

    const int nch = Ktot >> 5;
    loadG(0);
    storeS(0);
    __syncthreads();
    for (int c = 0; c < nch; c++) {
        if (c + 1 < nch) loadG(c + 1);
        mmaS(c & 1);
        if (c + 1 < nch) storeS((c + 1) & 1);
        __syncthreads();
    }

    // Epilogue
#pragma unroll
    for (int mt = 0; mt < 4; mt++) {
        int row0 = bm + warpM * 64 + mt * 16 + (lane >> 2);
#pragma unroll
        for (int nt = 0; nt < 4; nt++) {
            int col = bn + warpN * 32 + nt * 8 + (lane & 3) * 2;
            float bx = 0.f, by = 0.f;
            if (BIAS) { bx = __ldg(bias + col); by = __ldg(bias + col + 1); }
            float2 v0 = make_float2(acc[mt][nt][0] + bx, acc[mt][nt][1] + by);
            float2 v1 = make_float2(acc[mt][nt][2] + bx, acc[mt][nt][3] + by);
            if (RELU) {
                v0.x = fmaxf(v0.x, 0.f); v0.y = fmaxf(v0.y, 0.f);
                v1.x = fmaxf(v1.x, 0.f); v1.y = fmaxf(v1.y, 0.f);
            }
            if (row0 < M)     *(float2*)(C + (size_t)row0 * 256 + col) = v0;
            if (row0 + 8 < M) *(float2*)(C + (size_t)(row0 + 8) * 256 + col) = v1;
        }
    }
}

// ---------------------------------------------------------------------------
// Edge scatter: agg[rows[e]] += vals[e] * support[cols[e]]  (256 channels)
// 64 threads/edge; ONE red.global.add.v4.f32 per thread (1 L2 op per 16B
// instead of 4) — the L2 atomic ALU op count was the binding constraint.
// ---------------------------------------------------------------------------
__global__ __launch_bounds__(256) void scatter_kernel(
    const float* __restrict__ sup, const float* __restrict__ vals,
    const int* __restrict__ rows, const int* __restrict__ cols,
    float* __restrict__ agg)
{
    long long idx = (long long)blockIdx.x * blockDim.x + threadIdx.x;
    if (idx >= (long long)NE * 64) return;
    int e = (int)(idx >> 6);
    int q = (int)(idx & 63);
    int r = __ldg(rows + e);
    int c = __ldg(cols + e);
    float v = __ldg(vals + e);
    float4 s = __ldg((const float4*)(sup + (size_t)c * CCH) + q);
    float* dst = agg + (size_t)r * CCH + q * 4;
    asm volatile("red.global.add.v4.f32 [%0], {%1, %2, %3, %4};"
                 :: "l"(dst), "f"(v * s.x), "f"(v * s.y),
                    "f"(v * s.z), "f"(v * s.w)
                 : "memory");
}

// ---------------------------------------------------------------------------
extern "C" void kernel_launch(void* const* d_in, const int* in_sizes, int n_in,
                              void* d_out, int out_size)
{
    const float* x_t  = (const float*)d_in[0];
    const float* xs0  = (const float*)d_in[1];
    const float* xs1  = (const float*)d_in[2];
    const float* v0   = (const float*)d_in[3];
    const float* v1   = (const float*)d_in[4];
    const int*   r0   = (const int*)d_in[5];
    const int*   c0   = (const int*)d_in[6];
    const int*   r1   = (const int*)d_in[7];
    const int*   c1   = (const int*)d_in[8];
    const float* W0   = (const float*)d_in[9];
    const float* W1   = (const float*)d_in[10];
    const float* mW0  = (const float*)d_in[11];
    const float* mb0  = (const float*)d_in[12];
    const float* mW1  = (const float*)d_in[13];
    const float* mb1  = (const float*)d_in[14];
    const float* Wm   = (const float*)d_in[15];
    const float* bmv  = (const float*)d_in[16];
    float* out = (float*)d_out;

    float *sup0, *sup1, *a0, *b0, *a1, *b1;
    __nv_bfloat16 *wt0, *wt1, *mwt0, *mwt1, *wmt;
    cudaGetSymbolAddress((void**)&sup0, g_sup0);
    cudaGetSymbolAddress((void**)&sup1, g_sup1);
    cudaGetSymbolAddress((void**)&a0, g_a0);
    cudaGetSymbolAddress((void**)&b0, g_b0);
    cudaGetSymbolAddress((void**)&a1, g_a1);
    cudaGetSymbolAddress((void**)&b1, g_b1);
    cudaGetSymbolAddress((void**)&wt0, g_wt0);
    cudaGetSymbolAddress((void**)&wt1, g_wt1);
    cudaGetSymbolAddress((void**)&mwt0, g_mwt0);
    cudaGetSymbolAddress((void**)&mwt1, g_mwt1);
    cudaGetSymbolAddress((void**)&wmt, g_wmt);

    cudaFuncSetAttribute(mma_gemm<false, false>,
                         cudaFuncAttributeMaxDynamicSharedMemorySize, SMEMT);
    cudaFuncSetAttribute(mma_gemm<true, true>,
                         cudaFuncAttributeMaxDynamicSharedMemorySize, SMEMT);
    cudaFuncSetAttribute(mma_gemm<true, false>,
                         cudaFuncAttributeMaxDynamicSharedMemorySize, SMEMT);

    // ---- Weight prep: transpose + hi/lo bf16 split (batched) ----
    dim3 gp1((128 * 256 + 255) / 256, 1);
    prep_w<<<gp1, 256>>>(W0, wt0, wt0 + 256 * 128, 128);
    prep_w<<<gp1, 256>>>(W1, wt1, wt1 + 256 * 128, 128);
    dim3 gp3((256 * 256 + 255) / 256, 3);
    prep_w<<<gp3, 256>>>(mW0, mwt0, mwt0 + 65536, 256);
    prep_w<<<gp3, 256>>>(mW1, mwt1, mwt1 + 65536, 256);
    dim3 gpm((512 * 256 + 255) / 256, 1);
    prep_w<<<gpm, 256>>>(Wm, wmt, wmt + 256 * 512, 512);

    dim3 blk(256);
    dim3 gS((NS + 127) / 128, 2);   // support GEMMs: 782 x 2
    dim3 gT((NT + 127) / 128, 2);   // target GEMMs:  391 x 2

    // support = x_src @ W
    mma_gemm<false, false><<<gS, blk, SMEMT>>>(
        xs0, nullptr, wt0, wt0 + 256 * 128, nullptr, sup0, NS, 128, 128);
    mma_gemm<false, false><<<gS, blk, SMEMT>>>(
        xs1, nullptr, wt1, wt1 + 256 * 128, nullptr, sup1, NS, 128, 128);

    // agg init = x_target (epsilon = 0)
    cudaMemcpyAsync(a0, x_t, sizeof(float) * (size_t)NT * CCH, cudaMemcpyDeviceToDevice);
    cudaMemcpyAsync(a1, x_t, sizeof(float) * (size_t)NT * CCH, cudaMemcpyDeviceToDevice);

    // sparse scatter-add (vectorized reductions)
    int sblocks = (int)(((long long)NE * 64 + 255) / 256);
    scatter_kernel<<<sblocks, blk>>>(sup0, v0, r0, c0, a0);
    scatter_kernel<<<sblocks, blk>>>(sup1, v1, r1, c1, a1);

    // MLP branch 0: a0 -> b0 -> a0 -> b0
    mma_gemm<true, true><<<gT, blk, SMEMT>>>(
        a0, nullptr, mwt0, mwt0 + 65536, mb0, b0, NT, 256, 256);
    mma_gemm<true, true><<<gT, blk, SMEMT>>>(
        b0, nullptr, mwt0 + 2 * 65536, mwt0 + 3 * 65536, mb0 + 256, a0, NT, 256, 256);
    mma_gemm<true, true><<<gT, blk, SMEMT>>>(
        a0, nullptr, mwt0 + 4 * 65536, mwt0 + 5 * 65536, mb0 + 512, b0, NT, 256, 256);

    // MLP branch 1: a1 -> b1 -> a1 -> b1
    mma_gemm<true, true><<<gT, blk, SMEMT>>>(
        a1, nullptr, mwt1, mwt1 + 65536, mb1, b1, NT, 256, 256);
    mma_gemm<true, true><<<gT, blk, SMEMT>>>(
        b1, nullptr, mwt1 + 2 * 65536, mwt1 + 3 * 65536, mb1 + 256, a1, NT, 256, 256);
    mma_gemm<true, true><<<gT, blk, SMEMT>>>(
        a1, nullptr, mwt1 + 4 * 65536, mwt1 + 5 * 65536, mb1 + 512, b1, NT, 256, 256);

    // merge: out = [h0, h1] @ Wm + bm   (single K=512 GEMM, dual A sources)
    mma_gemm<true, false><<<gT, blk, SMEMT>>>(
        b0, b1, wmt, wmt + 256 * 512, bmv, out, NT, 512, 256);
}